// round 5
// baseline (speedup 1.0000x reference)
#include <cuda_runtime.h>

// DistPtsTopo: cell-binned (index bins), 3-kernel pipeline, self-resetting scratch.
// inputs: d_in[0] = offset (3,65,65,65) f32, d_in[1] = points (300000,3) f32
// output: (64^3, 48) f32 per-cell summed squared distances.

#define NN      65
#define NN2     (NN*NN)
#define NN3     (NN*NN*NN)
#define PTS     300000
#define NCELL   (64*64*64)       // 262144
#define CAP     16               // Poisson(1.145): P(count>=16) ~ 1e-13
#define NBUCKET 17               // counts 0..16
#define BPAD    32

// scratch (static device globals, zero-initialized at module load)
__device__ unsigned int g_cnt[NCELL];                    // reset by k_scatter each call
__device__ unsigned int g_cursor[BPAD];                  // reset by k_bin each call
__device__ unsigned int g_celllist[NBUCKET][NCELL];      // fixed region per bucket
__device__ unsigned int g_binidx[NCELL * CAP];           // point indices, 16 MB

// ---------------- kernel 1: bin points (4 pts/thread, float4 loads) ----------------
__global__ __launch_bounds__(256) void k_bin(const float* __restrict__ points) {
    int t = blockIdx.x * blockDim.x + threadIdx.x;
    if (blockIdx.x == 0 && threadIdx.x < BPAD) g_cursor[threadIdx.x] = 0u;
    int p0 = 4 * t;
    if (p0 >= PTS) return;

    const float4* pts4 = (const float4*)points;
    float4 va = __ldg(pts4 + 3 * t + 0);
    float4 vb = __ldg(pts4 + 3 * t + 1);
    float4 vc = __ldg(pts4 + 3 * t + 2);

    float x[4] = {va.x, va.w, vb.z, vc.y};
    float y[4] = {va.y, vb.x, vb.w, vc.z};
    float z[4] = {va.z, vb.y, vc.x, vc.w};

#pragma unroll
    for (int i = 0; i < 4; i++) {
        int ci = min(max(__float2int_rd(x[i]), 0), NN - 2);
        int cj = min(max(__float2int_rd(y[i]), 0), NN - 2);
        int ck = min(max(__float2int_rd(z[i]), 0), NN - 2);
        int c = (ci * 64 + cj) * 64 + ck;
        unsigned int slot = atomicAdd(&g_cnt[c], 1u);
        if (slot < CAP) g_binidx[c * CAP + slot] = (unsigned int)(p0 + i);
    }
}

// ---------------- kernel 2: scatter cells into bucket regions (and reset g_cnt) ----
__global__ __launch_bounds__(256) void k_scatter(void) {
    __shared__ unsigned int s_cnt[NBUCKET];
    __shared__ unsigned int s_base[NBUCKET];
    if (threadIdx.x < NBUCKET) s_cnt[threadIdx.x] = 0u;
    __syncthreads();
    int c = blockIdx.x * blockDim.x + threadIdx.x;   // grid covers exactly NCELL
    unsigned int n = min(g_cnt[c], (unsigned int)CAP);
    g_cnt[c] = 0u;                                   // self-reset for next call
    unsigned int r = atomicAdd(&s_cnt[n], 1u);       // intra-block rank
    __syncthreads();
    if (threadIdx.x < NBUCKET && s_cnt[threadIdx.x])
        s_base[threadIdx.x] = atomicAdd(&g_cursor[threadIdx.x], s_cnt[threadIdx.x]);
    __syncthreads();
    g_celllist[n][s_base[n] + r] = (unsigned int)c;
}

// ---------------- kernel 3: main — one thread per cell, bucket-uniform warps ------
__global__ __launch_bounds__(256) void k_main(
    const float* __restrict__ offset,
    const float* __restrict__ points,
    float* __restrict__ out)
{
    __shared__ unsigned int s_cur[NBUCKET];
    __shared__ unsigned int pre[NBUCKET + 1];
    if (threadIdx.x < NBUCKET) s_cur[threadIdx.x] = g_cursor[threadIdx.x];
    __syncthreads();
    if (threadIdx.x == 0) {
        unsigned int run = 0;
        #pragma unroll
        for (int b = 0; b < NBUCKET; b++) { pre[b] = run; run += s_cur[b]; }
        pre[NBUCKET] = run;    // == NCELL
    }
    __syncthreads();

    int t = blockIdx.x * blockDim.x + threadIdx.x;   // grid covers exactly NCELL
    int n = 0;
    #pragma unroll
    for (int b = 1; b < NBUCKET; b++) n += (t >= (int)pre[b]);
    int c = (int)g_celllist[n][t - pre[n]];

    float acc[48];
#pragma unroll
    for (int i = 0; i < 48; i++) acc[i] = 0.f;

    if (n > 0) {
        int ci = c >> 12;
        int cj = (c >> 6) & 63;
        int ck = c & 63;

        // per-cell: gather 24 offsets once
        int base = (ci * NN + cj) * NN + ck;
        const int COFF[8] = {0, 1, NN, NN + 1, NN2, NN2 + 1, NN2 + NN, NN2 + NN + 1};
        float off[3][8];
#pragma unroll
        for (int d = 0; d < 3; d++) {
            const float* o = offset + d * NN3 + base;
#pragma unroll
            for (int k = 0; k < 8; k++) off[d][k] = __ldg(o + COFF[k]);
        }

        const int EA[12] = {0, 0, 0, 1, 1, 2, 2, 3, 4, 4, 5, 6};
        const int EB[12] = {1, 2, 4, 3, 5, 3, 6, 7, 5, 6, 7, 7};
        const int ES[12][3] = {
            {0,0,1},{0,1,0},{1,0,0},{0,1,2},{1,0,2},{0,2,1},
            {1,2,0},{1,2,2},{2,0,1},{2,1,0},{2,1,2},{2,2,1}};

        // per-cell: S6[e][d] = (off_a + off_b)/6
        float S6[12][3];
#pragma unroll
        for (int ee = 0; ee < 12; ee++)
#pragma unroll
            for (int d = 0; d < 3; d++)
                S6[ee][d] = (off[d][EA[ee]] + off[d][EB[ee]]) * (1.f / 6.f);

        const int TA[48] = {1,1,1,1,1,1,1,1,1,1,
                            2,2,2,2,2,2,2,2,2,
                            3,3,3,3,3,3,3,3,
                            4,4,4,4,4,4,4,
                            5,5,5,5,5,5,
                            6,6,6,6,6,
                            7,7,7};
        const int TB[48] = {2,3,4,5,6,7,8,9,10,11,
                            3,4,5,6,7,8,9,10,11,
                            4,5,6,7,8,9,10,11,
                            5,6,7,8,9,10,11,
                            6,7,8,9,10,11,
                            7,8,9,10,11,
                            8,9,10};

        const unsigned int* bin = g_binidx + c * CAP;
        for (int s = 0; s < n; s++) {
            unsigned int pidx = __ldg(bin + s);
            float rx = __ldg(points + 3 * pidx + 0) - (float)ci;
            float ry = __ldg(points + 3 * pidx + 1) - (float)cj;
            float rz = __ldg(points + 3 * pidx + 2) - (float)ck;

            // A[d][sum] = r_d/3 - sum/6
            float A[3][3];
            {
                float r3x = rx * (1.f / 3.f), r3y = ry * (1.f / 3.f), r3z = rz * (1.f / 3.f);
                A[0][0] = r3x; A[0][1] = r3x - (1.f / 6.f); A[0][2] = r3x - (1.f / 3.f);
                A[1][0] = r3y; A[1][1] = r3y - (1.f / 6.f); A[1][2] = r3y - (1.f / 3.f);
                A[2][0] = r3z; A[2][1] = r3z - (1.f / 6.f); A[2][2] = r3z - (1.f / 3.f);
            }

            float w[12][3];
#pragma unroll
            for (int ee = 0; ee < 12; ee++)
#pragma unroll
                for (int d = 0; d < 3; d++)
                    w[ee][d] = A[d][ES[ee][d]] - S6[ee][d];

            // all 48 tris contain edge 0: q[a] = w0 + wa
            float q[7][3];
#pragma unroll
            for (int a = 1; a <= 7; a++)
#pragma unroll
                for (int d = 0; d < 3; d++) q[a - 1][d] = w[0][d] + w[a][d];

#pragma unroll
            for (int tt = 0; tt < 48; tt++) {
                int a = TA[tt] - 1, b = TB[tt];
                float sx = q[a][0] + w[b][0];
                float sy = q[a][1] + w[b][1];
                float sz = q[a][2] + w[b][2];
                acc[tt] += fmaf(sx, sx, fmaf(sy, sy, sz * sz));
            }
        }
    }

    // write full 48-float row (zeros for empty cells)
    float4* orow = (float4*)(out + (size_t)c * 48);
#pragma unroll
    for (int v = 0; v < 12; v++)
        orow[v] = make_float4(acc[4 * v], acc[4 * v + 1], acc[4 * v + 2], acc[4 * v + 3]);
}

extern "C" void kernel_launch(void* const* d_in, const int* in_sizes, int n_in,
                              void* d_out, int out_size) {
    const float* offset = (const float*)d_in[0];
    const float* points = (const float*)d_in[1];
    float* out = (float*)d_out;

    k_bin<<<(PTS / 4 + 255) / 256, 256>>>(points);
    k_scatter<<<NCELL / 256, 256>>>();
    k_main<<<NCELL / 256, 256>>>(offset, points, out);
}

// round 6
// speedup vs baseline: 1.2000x; 1.2000x over previous
#include <cuda_runtime.h>

// DistPtsTopo: cell-binned (float4 coord bins), 3-kernel pipeline,
// warp-cooperative coalesced output stores.
// inputs: d_in[0] = offset (3,65,65,65) f32, d_in[1] = points (300000,3) f32
// output: (64^3, 48) f32 per-cell summed squared distances.

#define NN      65
#define NN2     (NN*NN)
#define NN3     (NN*NN*NN)
#define PTS     300000
#define NCELL   (64*64*64)       // 262144
#define CAP     16               // Poisson(1.145): P(count>=16) ~ 1e-13
#define NBUCKET 17               // counts 0..16
#define BPAD    32
#define MTPB    128              // k_main threads/block (4 warps)

// scratch (static device globals, zero-initialized at module load)
__device__ unsigned int g_cnt[NCELL];                    // reset by k_scatter each call
__device__ unsigned int g_cursor[BPAD];                  // reset by k_bin each call
__device__ unsigned int g_celllist[NBUCKET][NCELL];      // fixed region per bucket
__device__ float4       g_bins[NCELL * CAP];             // binned point coords, 64 MB

// ---------------- kernel 1: bin points (2 pts/thread, float2 loads) ----------------
__global__ __launch_bounds__(256) void k_bin(const float* __restrict__ points) {
    int t = blockIdx.x * blockDim.x + threadIdx.x;
    if (blockIdx.x == 0 && threadIdx.x < BPAD) g_cursor[threadIdx.x] = 0u;
    int p0 = 2 * t;
    if (p0 >= PTS) return;

    const float2* pts2 = (const float2*)points;   // 3*p0 floats = 3*t float2s, 8B aligned
    float2 a = __ldg(pts2 + 3 * t + 0);
    float2 b = __ldg(pts2 + 3 * t + 1);
    float2 d2 = __ldg(pts2 + 3 * t + 2);

    float x[2] = {a.x, b.y};
    float y[2] = {a.y, d2.x};
    float z[2] = {b.x, d2.y};

#pragma unroll
    for (int i = 0; i < 2; i++) {
        int ci = min(max(__float2int_rd(x[i]), 0), NN - 2);
        int cj = min(max(__float2int_rd(y[i]), 0), NN - 2);
        int ck = min(max(__float2int_rd(z[i]), 0), NN - 2);
        int c = (ci * 64 + cj) * 64 + ck;
        unsigned int slot = atomicAdd(&g_cnt[c], 1u);
        if (slot < CAP) g_bins[c * CAP + slot] = make_float4(x[i], y[i], z[i], 0.f);
    }
}

// ---------------- kernel 2: scatter cells into bucket regions (and reset g_cnt) ----
__global__ __launch_bounds__(256) void k_scatter(void) {
    __shared__ unsigned int s_cnt[NBUCKET];
    __shared__ unsigned int s_base[NBUCKET];
    if (threadIdx.x < NBUCKET) s_cnt[threadIdx.x] = 0u;
    __syncthreads();
    int c = blockIdx.x * blockDim.x + threadIdx.x;   // grid covers exactly NCELL
    unsigned int n = min(g_cnt[c], (unsigned int)CAP);
    g_cnt[c] = 0u;                                   // self-reset for next call
    unsigned int r = atomicAdd(&s_cnt[n], 1u);       // intra-block rank
    __syncthreads();
    if (threadIdx.x < NBUCKET && s_cnt[threadIdx.x])
        s_base[threadIdx.x] = atomicAdd(&g_cursor[threadIdx.x], s_cnt[threadIdx.x]);
    __syncthreads();
    g_celllist[n][s_base[n] + r] = (unsigned int)c;
}

// ---------------- kernel 3: main — one thread per cell, bucket-uniform warps,
//                  warp-cooperative coalesced row stores ------
__global__ __launch_bounds__(MTPB) void k_main(
    const float* __restrict__ offset,
    float* __restrict__ out)
{
    __shared__ float        s_row[(MTPB / 32)][48 * 33];   // [warp][f*33 + lane]
    __shared__ unsigned int s_cell[(MTPB / 32)][32];
    __shared__ unsigned int pre[NBUCKET + 1];

    if (threadIdx.x == 0) {
        unsigned int run = 0;
        #pragma unroll
        for (int b = 0; b < NBUCKET; b++) { pre[b] = run; run += g_cursor[b]; }
        pre[NBUCKET] = run;    // == NCELL
    }
    __syncthreads();

    int t = blockIdx.x * blockDim.x + threadIdx.x;   // grid covers exactly NCELL
    int lane = threadIdx.x & 31;
    int warp = threadIdx.x >> 5;

    int n = 0;
    #pragma unroll
    for (int b = 1; b < NBUCKET; b++) n += (t >= (int)pre[b]);
    int c = (int)g_celllist[n][t - pre[n]];

    float acc[48];
#pragma unroll
    for (int i = 0; i < 48; i++) acc[i] = 0.f;

    if (n > 0) {
        int ci = c >> 12;
        int cj = (c >> 6) & 63;
        int ck = c & 63;

        // per-cell: gather 24 offsets once
        int base = (ci * NN + cj) * NN + ck;
        const int COFF[8] = {0, 1, NN, NN + 1, NN2, NN2 + 1, NN2 + NN, NN2 + NN + 1};
        float off[3][8];
#pragma unroll
        for (int d = 0; d < 3; d++) {
            const float* o = offset + d * NN3 + base;
#pragma unroll
            for (int k = 0; k < 8; k++) off[d][k] = __ldg(o + COFF[k]);
        }

        const int EA[12] = {0, 0, 0, 1, 1, 2, 2, 3, 4, 4, 5, 6};
        const int EB[12] = {1, 2, 4, 3, 5, 3, 6, 7, 5, 6, 7, 7};
        const int ES[12][3] = {
            {0,0,1},{0,1,0},{1,0,0},{0,1,2},{1,0,2},{0,2,1},
            {1,2,0},{1,2,2},{2,0,1},{2,1,0},{2,1,2},{2,2,1}};

        // per-cell: S6[e][d] = (off_a + off_b)/6
        float S6[12][3];
#pragma unroll
        for (int ee = 0; ee < 12; ee++)
#pragma unroll
            for (int d = 0; d < 3; d++)
                S6[ee][d] = (off[d][EA[ee]] + off[d][EB[ee]]) * (1.f / 6.f);

        const int TA[48] = {1,1,1,1,1,1,1,1,1,1,
                            2,2,2,2,2,2,2,2,2,
                            3,3,3,3,3,3,3,3,
                            4,4,4,4,4,4,4,
                            5,5,5,5,5,5,
                            6,6,6,6,6,
                            7,7,7};
        const int TB[48] = {2,3,4,5,6,7,8,9,10,11,
                            3,4,5,6,7,8,9,10,11,
                            4,5,6,7,8,9,10,11,
                            5,6,7,8,9,10,11,
                            6,7,8,9,10,11,
                            7,8,9,10,11,
                            8,9,10};

        const float4* bin = g_bins + c * CAP;
        for (int s = 0; s < n; s++) {
            float4 p4 = __ldg(bin + s);
            float rx = p4.x - (float)ci;
            float ry = p4.y - (float)cj;
            float rz = p4.z - (float)ck;

            // A[d][sum] = r_d/3 - sum/6
            float A[3][3];
            {
                float r3x = rx * (1.f / 3.f), r3y = ry * (1.f / 3.f), r3z = rz * (1.f / 3.f);
                A[0][0] = r3x; A[0][1] = r3x - (1.f / 6.f); A[0][2] = r3x - (1.f / 3.f);
                A[1][0] = r3y; A[1][1] = r3y - (1.f / 6.f); A[1][2] = r3y - (1.f / 3.f);
                A[2][0] = r3z; A[2][1] = r3z - (1.f / 6.f); A[2][2] = r3z - (1.f / 3.f);
            }

            float w[12][3];
#pragma unroll
            for (int ee = 0; ee < 12; ee++)
#pragma unroll
                for (int d = 0; d < 3; d++)
                    w[ee][d] = A[d][ES[ee][d]] - S6[ee][d];

            // all 48 tris contain edge 0: q[a] = w0 + wa
            float q[7][3];
#pragma unroll
            for (int a = 1; a <= 7; a++)
#pragma unroll
                for (int d = 0; d < 3; d++) q[a - 1][d] = w[0][d] + w[a][d];

#pragma unroll
            for (int tt = 0; tt < 48; tt++) {
                int a = TA[tt] - 1, b = TB[tt];
                float sx = q[a][0] + w[b][0];
                float sy = q[a][1] + w[b][1];
                float sz = q[a][2] + w[b][2];
                acc[tt] += fmaf(sx, sx, fmaf(sy, sy, sz * sz));
            }
        }
    }

    // ---- warp-cooperative coalesced store of 32 rows x 48 floats ----
    // stage: s_row[warp][f*33 + lane] = acc[f]  (stride-33 -> conflict-free)
    float* sw = s_row[warp];
#pragma unroll
    for (int f = 0; f < 48; f++) sw[f * 33 + lane] = acc[f];
    s_cell[warp][lane] = (unsigned int)c;
    __syncwarp();

    // drain: flat index i over 32 rows x 48 floats, lane-contiguous -> coalesced
    for (int i = lane; i < 32 * 48; i += 32) {
        int row = i / 48;
        int f = i - row * 48;
        out[(size_t)s_cell[warp][row] * 48 + f] = sw[f * 33 + row];
    }
}

extern "C" void kernel_launch(void* const* d_in, const int* in_sizes, int n_in,
                              void* d_out, int out_size) {
    const float* offset = (const float*)d_in[0];
    const float* points = (const float*)d_in[1];
    float* out = (float*)d_out;

    k_bin<<<(PTS / 2 + 255) / 256, 256>>>(points);
    k_scatter<<<NCELL / 256, 256>>>();
    k_main<<<NCELL / MTPB, MTPB>>>(offset, out);
}

// round 7
// speedup vs baseline: 1.9553x; 1.6294x over previous
#include <cuda_runtime.h>

// DistPtsTopo via per-cell moment accumulation.
// Key identity: for tri t=(e0,a,b), centroid diff s = r - T_t with T_t per-cell const.
//   sum_p |r - T_t|^2 = Sum|r|^2 - 2 T_t . SumR + n |T_t|^2
// So k_bin only accumulates M=(SumRx,SumRy,SumRz,Sum|r|^2) and n per cell (REDs,
// no return), and k_main computes all 48 outputs per cell in closed form.
// inputs: d_in[0] = offset (3,65,65,65) f32, d_in[1] = points (300000,3) f32
// output: (64^3, 48) f32.

#define NN      65
#define NN2     (NN*NN)
#define NN3     (NN*NN*NN)
#define PTS     300000
#define NCELL   (64*64*64)       // 262144
#define MTPB    128

// scratch: zero at module load; k_main self-resets after reading.
__device__ float4 g_momA[NCELL];   // (SumRx, SumRy, SumRz, Sum|r|^2)
__device__ float  g_momN[NCELL];   // point count (exact as float)

// ---------------- kernel 1: accumulate per-cell moments (2 pts/thread) ------------
__global__ __launch_bounds__(256) void k_bin(const float* __restrict__ points) {
    int t = blockIdx.x * blockDim.x + threadIdx.x;
    int p0 = 2 * t;
    if (p0 >= PTS) return;

    const float2* pts2 = (const float2*)points;   // 3*t float2s per 2 points
    float2 a  = __ldg(pts2 + 3 * t + 0);
    float2 b  = __ldg(pts2 + 3 * t + 1);
    float2 c2 = __ldg(pts2 + 3 * t + 2);

    float x[2] = {a.x, b.y};
    float y[2] = {a.y, c2.x};
    float z[2] = {b.x, c2.y};

#pragma unroll
    for (int i = 0; i < 2; i++) {
        int ci = min(max(__float2int_rd(x[i]), 0), NN - 2);
        int cj = min(max(__float2int_rd(y[i]), 0), NN - 2);
        int ck = min(max(__float2int_rd(z[i]), 0), NN - 2);
        int c = (ci * 64 + cj) * 64 + ck;
        float rx = x[i] - (float)ci;
        float ry = y[i] - (float)cj;
        float rz = z[i] - (float)ck;
        float rr = fmaf(rx, rx, fmaf(ry, ry, rz * rz));
        asm volatile("red.global.add.v4.f32 [%0], {%1, %2, %3, %4};"
                     :: "l"(&g_momA[c]), "f"(rx), "f"(ry), "f"(rz), "f"(rr)
                     : "memory");
        asm volatile("red.global.add.f32 [%0], %1;"
                     :: "l"(&g_momN[c]), "f"(1.0f)
                     : "memory");
    }
}

// ---------------- kernel 2: per-cell closed form, one thread per cell -------------
__global__ __launch_bounds__(MTPB) void k_main(
    const float* __restrict__ offset,
    float* __restrict__ out)
{
    __shared__ float s_row[MTPB / 32][48 * 33];   // [warp][f*33 + lane]

    int t = blockIdx.x * blockDim.x + threadIdx.x;   // cell id, natural order
    int lane = threadIdx.x & 31;
    int warp = threadIdx.x >> 5;

    float4 M = g_momA[t];
    float  nM = g_momN[t];
    // self-reset for next kernel_launch call (graph replay)
    g_momA[t] = make_float4(0.f, 0.f, 0.f, 0.f);
    g_momN[t] = 0.f;

    int ci = t >> 12;
    int cj = (t >> 6) & 63;
    int ck = t & 63;

    // gather 24 offsets (fully coalesced: consecutive threads = consecutive ck)
    int base = (ci * NN + cj) * NN + ck;
    const int COFF[8] = {0, 1, NN, NN + 1, NN2, NN2 + 1, NN2 + NN, NN2 + NN + 1};
    float off[3][8];
#pragma unroll
    for (int d = 0; d < 3; d++) {
        const float* o = offset + d * NN3 + base;
#pragma unroll
        for (int k = 0; k < 8; k++) off[d][k] = __ldg(o + COFF[k]);
    }

    // edges (numpy enumeration order) + per-dim corner-coordinate sums
    const int EA[12] = {0, 0, 0, 1, 1, 2, 2, 3, 4, 4, 5, 6};
    const int EB[12] = {1, 2, 4, 3, 5, 3, 6, 7, 5, 6, 7, 7};
    const int ES[12][3] = {
        {0,0,1},{0,1,0},{1,0,0},{0,1,2},{1,0,2},{0,2,1},
        {1,2,0},{1,2,2},{2,0,1},{2,1,0},{2,1,2},{2,2,1}};

    // S6[e][d] = (off_a + off_b)/6
    float S6[12][3];
#pragma unroll
    for (int ee = 0; ee < 12; ee++)
#pragma unroll
        for (int d = 0; d < 3; d++)
            S6[ee][d] = (off[d][EA[ee]] + off[d][EB[ee]]) * (1.f / 6.f);

    const int TA[48] = {1,1,1,1,1,1,1,1,1,1,
                        2,2,2,2,2,2,2,2,2,
                        3,3,3,3,3,3,3,3,
                        4,4,4,4,4,4,4,
                        5,5,5,5,5,5,
                        6,6,6,6,6,
                        7,7,7};
    const int TB[48] = {2,3,4,5,6,7,8,9,10,11,
                        3,4,5,6,7,8,9,10,11,
                        4,5,6,7,8,9,10,11,
                        5,6,7,8,9,10,11,
                        6,7,8,9,10,11,
                        7,8,9,10,11,
                        8,9,10};

    float* sw = s_row[warp];
#pragma unroll
    for (int tt = 0; tt < 48; tt++) {
        int a = TA[tt], b = TB[tt];
        // T_t[d] = (ES0+ESa+ESb)[d]/6 + S6_0[d] + S6_a[d] + S6_b[d]
        float Tx = (float)(ES[0][0] + ES[a][0] + ES[b][0]) * (1.f / 6.f)
                 + S6[0][0] + S6[a][0] + S6[b][0];
        float Ty = (float)(ES[0][1] + ES[a][1] + ES[b][1]) * (1.f / 6.f)
                 + S6[0][1] + S6[a][1] + S6[b][1];
        float Tz = (float)(ES[0][2] + ES[a][2] + ES[b][2]) * (1.f / 6.f)
                 + S6[0][2] + S6[a][2] + S6[b][2];
        float U = fmaf(Tx, Tx, fmaf(Ty, Ty, Tz * Tz));
        // D = Sum|r|^2 - 2 T.SumR + n |T|^2   (M = 0 for empty cells -> D = 0)
        float D = fmaf(nM, U,
                  fmaf(-2.f * Tx, M.x,
                  fmaf(-2.f * Ty, M.y,
                  fmaf(-2.f * Tz, M.z, M.w))));
        sw[tt * 33 + lane] = D;
    }
    __syncwarp();

    // drain: rows are consecutive cells -> fully contiguous 6KB per warp
    size_t rowbase = (size_t)(blockIdx.x * MTPB + warp * 32) * 48;
    for (int i = lane; i < 32 * 48; i += 32) {
        int row = i / 48;
        int f = i - row * 48;
        out[rowbase + i] = sw[f * 33 + row];
    }
}

extern "C" void kernel_launch(void* const* d_in, const int* in_sizes, int n_in,
                              void* d_out, int out_size) {
    const float* offset = (const float*)d_in[0];
    const float* points = (const float*)d_in[1];
    float* out = (float*)d_out;

    k_bin<<<(PTS / 2 + 255) / 256, 256>>>(points);
    k_main<<<NCELL / MTPB, MTPB>>>(offset, out);
}

// round 9
// speedup vs baseline: 2.5135x; 1.2855x over previous
#include <cuda_runtime.h>

// DistPtsTopo via per-cell moments + separable tri factorization.
//   s_t = r - T_t,  T_t = F_0 + F_a + F_b,  F_e = ES_e/6 + (off_A(e)+off_B(e))/6
//   D_t = Mw + n|T|^2 - 2 T.M = alpha_a + beta_b + 2n (G_a . F_b),  G_a = F_0+F_a
// k_bin accumulates M=(SumR, Sum|r|^2) and n per cell via REDs (no return).
// k_main: one thread per cell, 5-instr inner loop, 128-bit smem transpose store.
// inputs: d_in[0] = offset (3,65,65,65) f32, d_in[1] = points (300000,3) f32
// output: (64^3, 48) f32.

#define NN      65
#define NN2     (NN*NN)
#define NN3     (NN*NN*NN)
#define PTS     300000
#define NCELL   (64*64*64)       // 262144
#define MTPB    128
#define PITCH   52               // 48 + 4 pad words: conflict-free 128-bit smem ops

// scratch: zero at module load; k_main self-resets after reading.
__device__ float4 g_momA[NCELL];   // (SumRx, SumRy, SumRz, Sum|r|^2)
__device__ float  g_momN[NCELL];   // point count

// ---------------- kernel 1: accumulate per-cell moments (2 pts/thread) ------------
__global__ __launch_bounds__(256) void k_bin(const float* __restrict__ points) {
    int t = blockIdx.x * blockDim.x + threadIdx.x;
    int p0 = 2 * t;
    if (p0 >= PTS) return;

    const float2* pts2 = (const float2*)points;
    float2 a  = __ldg(pts2 + 3 * t + 0);
    float2 b  = __ldg(pts2 + 3 * t + 1);
    float2 c2 = __ldg(pts2 + 3 * t + 2);

    float x[2] = {a.x, b.y};
    float y[2] = {a.y, c2.x};
    float z[2] = {b.x, c2.y};

#pragma unroll
    for (int i = 0; i < 2; i++) {
        int ci = min(max(__float2int_rd(x[i]), 0), NN - 2);
        int cj = min(max(__float2int_rd(y[i]), 0), NN - 2);
        int ck = min(max(__float2int_rd(z[i]), 0), NN - 2);
        int c = (ci * 64 + cj) * 64 + ck;
        float rx = x[i] - (float)ci;
        float ry = y[i] - (float)cj;
        float rz = z[i] - (float)ck;
        float rr = fmaf(rx, rx, fmaf(ry, ry, rz * rz));
        asm volatile("red.global.add.v4.f32 [%0], {%1, %2, %3, %4};"
                     :: "l"(&g_momA[c]), "f"(rx), "f"(ry), "f"(rz), "f"(rr)
                     : "memory");
        asm volatile("red.global.add.f32 [%0], %1;"
                     :: "l"(&g_momN[c]), "f"(1.0f)
                     : "memory");
    }
}

// ---------------- kernel 2: per-cell closed form, one thread per cell -------------
__global__ __launch_bounds__(MTPB) void k_main(
    const float* __restrict__ offset,
    float* __restrict__ out)
{
    __shared__ float s_row[MTPB / 32][32 * PITCH];

    int t = blockIdx.x * blockDim.x + threadIdx.x;   // cell id, natural order
    int lane = threadIdx.x & 31;
    int warp = threadIdx.x >> 5;

    float4 M = g_momA[t];
    float  nM = g_momN[t];
    g_momA[t] = make_float4(0.f, 0.f, 0.f, 0.f);     // self-reset for graph replay
    g_momN[t] = 0.f;

    float M2x = -2.f * M.x, M2y = -2.f * M.y, M2z = -2.f * M.z;
    float n2 = 2.f * nM;

    int ci = t >> 12;
    int cj = (t >> 6) & 63;
    int ck = t & 63;

    // gather 24 offsets (coalesced in ck)
    int base = (ci * NN + cj) * NN + ck;
    const int COFF[8] = {0, 1, NN, NN + 1, NN2, NN2 + 1, NN2 + NN, NN2 + NN + 1};
    float off[3][8];
#pragma unroll
    for (int d = 0; d < 3; d++) {
        const float* o = offset + d * NN3 + base;
#pragma unroll
        for (int k = 0; k < 8; k++) off[d][k] = __ldg(o + COFF[k]);
    }

    // edges (numpy enumeration order) + per-dim corner-coordinate sums
    const int EA[12] = {0, 0, 0, 1, 1, 2, 2, 3, 4, 4, 5, 6};
    const int EB[12] = {1, 2, 4, 3, 5, 3, 6, 7, 5, 6, 7, 7};
    const int ES[12][3] = {
        {0,0,1},{0,1,0},{1,0,0},{0,1,2},{1,0,2},{0,2,1},
        {1,2,0},{1,2,2},{2,0,1},{2,1,0},{2,1,2},{2,2,1}};

    // F_e[d] = ES_e[d]/6 + (off_A + off_B)/6
    float F[12][3];
#pragma unroll
    for (int e = 0; e < 12; e++)
#pragma unroll
        for (int d = 0; d < 3; d++)
            F[e][d] = fmaf(off[d][EA[e]] + off[d][EB[e]], (1.f / 6.f),
                           (float)ES[e][d] * (1.f / 6.f));

    // beta_b = n|F_b|^2 + F_b . M2   (b = 2..11)
    float beta[12];
#pragma unroll
    for (int b = 2; b < 12; b++) {
        float ff = fmaf(F[b][0], F[b][0], fmaf(F[b][1], F[b][1], F[b][2] * F[b][2]));
        float fd = fmaf(F[b][0], M2x, fmaf(F[b][1], M2y, F[b][2] * M2z));
        beta[b] = fmaf(nM, ff, fd);
    }

    float* sw = s_row[warp] + lane * PITCH;
    float d4[4];
    int tt = 0;

#pragma unroll
    for (int a = 1; a <= 7; a++) {
        float Gx = F[0][0] + F[a][0];
        float Gy = F[0][1] + F[a][1];
        float Gz = F[0][2] + F[a][2];
        float gg = fmaf(Gx, Gx, fmaf(Gy, Gy, Gz * Gz));
        float gd = fmaf(Gx, M2x, fmaf(Gy, M2y, Gz * M2z));
        float alpha = fmaf(nM, gg, M.w + gd);
        float Hx = n2 * Gx, Hy = n2 * Gy, Hz = n2 * Gz;
#pragma unroll
        for (int b = a + 1; b < 12; b++) {
            if (a == 7 && b == 11) break;   // 48 tris total (lex-truncated)
            float ab = alpha + beta[b];
            float D = fmaf(Hx, F[b][0], fmaf(Hy, F[b][1], fmaf(Hz, F[b][2], ab)));
            d4[tt & 3] = D;
            if ((tt & 3) == 3)
                *(float4*)(sw + (tt - 3)) = make_float4(d4[0], d4[1], d4[2], d4[3]);
            tt++;
        }
    }
    __syncwarp();

    // drain: warp's 32 rows are consecutive cells -> 6KB contiguous, float4 ops
    const float* swb = s_row[warp];
    float4* out4 = (float4*)out + (size_t)(blockIdx.x * MTPB + warp * 32) * 12;
#pragma unroll
    for (int j = 0; j < 12; j++) {
        int g4 = 32 * j + lane;          // 0..383 float4s
        int row = g4 / 12;
        int k = g4 - 12 * row;
        out4[g4] = *(const float4*)(swb + row * PITCH + 4 * k);
    }
}

extern "C" void kernel_launch(void* const* d_in, const int* in_sizes, int n_in,
                              void* d_out, int out_size) {
    const float* offset = (const float*)d_in[0];
    const float* points = (const float*)d_in[1];
    float* out = (float*)d_out;

    k_bin<<<(PTS / 2 + 255) / 256, 256>>>(points);
    k_main<<<NCELL / MTPB, MTPB>>>(offset, out);
}